// round 12
// baseline (speedup 1.0000x reference)
#include <cuda_runtime.h>
#include <cstdint>

// LSTM B=128, T=2048, F=3, U=256. 128 plain CTAs = 16 groups x 8 rank-CTAs.
// CTA: 8 batch rows x 32 units (128 permuted gate cols), Wh slice resident in SMEM (128KB).
// R6: NO global barrier. Per-rank monotonic flags + slice publish through L2.
//     GEMM processed as 8 rank-chunks of 32 k; own chunk needs no global traffic;
//     remote chunk (r+1) flag-poll + LDG overlap the FFMA of chunk r.
//     FFMA2 (packed fp32x2, bit-exact) GEMM with duplicated-h pairs.

#define BB 128
#define TT 2048
#define FF 3
#define UU 256
#define G4 1024
#define NCTA 128
#define NTHR 256

__device__ float    g_hx[2][16][8][256];   // [slot][group][rank][b*32+u]
__device__ unsigned g_flag[16][8][32];     // [group][rank][pad] : 128B-spaced flags

// SMEM layout (float offsets)
#define OFF_WH   0        // 256*128 = 32768 : whs[k][u_l*4+gate] (permuted)
#define OFF_HD   32768    // 8*516   = 4128  : hd[b][2k] = {h_k,h_k}, row stride 516
#define OFF_BIAS 36896    // 128 (permuted)
#define OFF_WX   37024    // 384 (permuted)
#define SMEM_FLOATS 37408
#define SMEM_BYTES (SMEM_FLOATS * 4)
#define HSTRIDE 516

__device__ __forceinline__ float sig_f(float x) {
    x = fminf(fmaxf(x, -30.f), 30.f);
    float e = __expf(-x);
    return __fdividef(1.f, 1.f + e);
}
__device__ __forceinline__ float tanh_f(float x) {
    float ax = fminf(fabsf(x), 15.f);
    float e = __expf(-2.f * ax);
    float r = __fdividef(1.f - e, 1.f + e);
    return copysignf(r, x);
}
__device__ __forceinline__ void ffma2(unsigned long long& acc,
                                      unsigned long long a,
                                      unsigned long long b) {
    asm("fma.rn.f32x2 %0, %1, %2, %0;" : "+l"(acc) : "l"(a), "l"(b));
}
__device__ __forceinline__ void wait_flag(const unsigned* fp, unsigned need) {
    unsigned v;
    do {
        asm volatile("ld.global.acquire.gpu.u32 %0, [%1];" : "=r"(v) : "l"(fp));
    } while (v < need);
}

// one 32-k chunk of the GEMM: k in [r*32, r*32+32)
__device__ __forceinline__ void gemm_chunk(const float* __restrict__ whp,
                                           const float* __restrict__ hrow, int r,
                                           unsigned long long& a01,
                                           unsigned long long& a23) {
    const float* wk = whp + (r * 32) * 128;
    const ulonglong2* hp = reinterpret_cast<const ulonglong2*>(hrow + r * 64);
    #pragma unroll
    for (int q = 0; q < 16; q++) {                 // 2 k per iter
        ulonglong2 hv = hp[q];                     // {h0,h0},{h1,h1}
        ulonglong2 w0 = *reinterpret_cast<const ulonglong2*>(wk + (2 * q)     * 128);
        ulonglong2 w1 = *reinterpret_cast<const ulonglong2*>(wk + (2 * q + 1) * 128);
        ffma2(a01, hv.x, w0.x);
        ffma2(a23, hv.x, w0.y);
        ffma2(a01, hv.y, w1.x);
        ffma2(a23, hv.y, w1.y);
    }
}

__global__ void lstm_init_kernel() {
    int i = blockIdx.x * blockDim.x + threadIdx.x;
    float* h = (float*)g_hx;
    if (i < 2 * 16 * 8 * 256) h[i] = 0.f;
    if (i < 16 * 8 * 32) ((unsigned*)g_flag)[i] = 0u;
}

__global__ void __launch_bounds__(NTHR, 1) lstm_persistent_kernel(
    const float* __restrict__ x,     // [B, T, F]
    const float* __restrict__ Wx,    // [F, 4U]
    const float* __restrict__ Wh,    // [U, 4U]
    const float* __restrict__ bias,  // [4U]
    float* __restrict__ out,         // ys [B,T,U] (+ h_T, c_T if write_hc)
    int write_hc)
{
    extern __shared__ float sm[];
    float* whs = sm + OFF_WH;
    float* hd  = sm + OFF_HD;
    float* bs  = sm + OFF_BIAS;
    float* wxs = sm + OFF_WX;

    const int tid = threadIdx.x;
    const int RB  = blockIdx.x >> 3;   // group 0..15
    const int CB  = blockIdx.x & 7;    // rank within group
    const int gb  = RB * 8;            // global batch base

    // ---------------- setup: permuted weights -> SMEM ----------------
    #pragma unroll
    for (int g = 0; g < 4; g++) {
        const int gbase = g * UU + CB * 32;
        for (int i = tid; i < 256 * 32; i += NTHR) {
            int k = i >> 5, ul = i & 31;
            whs[k * 128 + ul * 4 + g] = Wh[k * G4 + gbase + ul];
        }
        for (int i = tid; i < 3 * 32; i += NTHR) {
            int f = i >> 5, ul = i & 31;
            wxs[f * 128 + ul * 4 + g] = Wx[f * G4 + gbase + ul];
        }
    }
    if (tid < 128) {
        int ul = tid >> 2, g = tid & 3;
        bs[tid] = bias[g * UU + CB * 32 + ul];
    }
    for (int i = tid; i < 8 * HSTRIDE; i += NTHR) hd[i] = 0.f;   // step-0 h = 0

    const int u_l = tid >> 3;   // 0..31
    const int b_l = tid & 7;    // 0..7
    const int gcol = CB * 32 + u_l;
    const float* whp  = whs + u_l * 4;
    const float* hrow = hd + b_l * HSTRIDE;

    unsigned* myflag = &g_flag[RB][CB][0];

    // staging-thread mapping (tid < 64): batch row sb, float4 index sq
    const int sb = tid >> 3;
    const int sq = tid & 7;
    float* sdst = hd + sb * HSTRIDE + sq * 8;   // + r*64 later

    float c = 0.f;
    float xp0, xp1, xp2;
    {
        const float* xr = x + (size_t)(gb + b_l) * (TT * FF);
        xp0 = __ldg(xr + 0); xp1 = __ldg(xr + 1); xp2 = __ldg(xr + 2);
    }

    __syncthreads();   // setup visible

    for (int s = 0; s < TT; s++) {
        const int p  = s & 1;
        const int pn = p ^ 1;

        // publish flag for this step's h (stored to L2 in previous epilogue)
        if (tid == 0 && s > 0) {
            __threadfence();
            *(volatile unsigned*)myflag = (unsigned)s;
        }

        // -------- acc init: bias + x @ Wx (packed) --------
        unsigned long long a01, a23;
        {
            ulonglong2 bb = *reinterpret_cast<const ulonglong2*>(bs + u_l * 4);
            a01 = bb.x; a23 = bb.y;
            unsigned long long xx0, xx1, xx2;
            asm("mov.b64 %0, {%1, %1};" : "=l"(xx0) : "f"(xp0));
            asm("mov.b64 %0, {%1, %1};" : "=l"(xx1) : "f"(xp1));
            asm("mov.b64 %0, {%1, %1};" : "=l"(xx2) : "f"(xp2));
            ulonglong2 w;
            w = *reinterpret_cast<const ulonglong2*>(wxs + 0 * 128 + u_l * 4);
            ffma2(a01, xx0, w.x); ffma2(a23, xx0, w.y);
            w = *reinterpret_cast<const ulonglong2*>(wxs + 1 * 128 + u_l * 4);
            ffma2(a01, xx1, w.x); ffma2(a23, xx1, w.y);
            w = *reinterpret_cast<const ulonglong2*>(wxs + 2 * 128 + u_l * 4);
            ffma2(a01, xx2, w.x); ffma2(a23, xx2, w.y);
        }

        // prefetch next x (L1-cacheable, consumed next step)
        if (s + 1 < TT) {
            const float* xr = x + (size_t)(gb + b_l) * (TT * FF) + (size_t)(s + 1) * FF;
            xp0 = __ldg(xr + 0); xp1 = __ldg(xr + 1); xp2 = __ldg(xr + 2);
        }

        // -------- stage first remote chunk (overlaps own-chunk compute) --------
        const float* slotbase = &g_hx[p][RB][0][0];
        float4 ldv;
        {
            int r1 = (CB + 1) & 7;
            if (tid < 64) {
                if (s > 0) wait_flag(&g_flag[RB][r1][0], (unsigned)s);
                ldv = __ldcg(reinterpret_cast<const float4*>(
                          slotbase + r1 * 256 + sb * 32 + sq * 4));
            }
        }

        // -------- own chunk (no global traffic) --------
        gemm_chunk(whp, hrow, CB, a01, a23);

        // -------- remaining 7 chunks, software-pipelined --------
        #pragma unroll 1
        for (int ci = 1; ci < 8; ci++) {
            int r = (CB + ci) & 7;
            if (tid < 64) {
                float* d = sdst + r * 64;
                *reinterpret_cast<float4*>(d + 0) = make_float4(ldv.x, ldv.x, ldv.y, ldv.y);
                *reinterpret_cast<float4*>(d + 4) = make_float4(ldv.z, ldv.z, ldv.w, ldv.w);
                if (ci < 7) {
                    int rn = (CB + ci + 1) & 7;
                    if (s > 0) wait_flag(&g_flag[RB][rn][0], (unsigned)s);
                    ldv = __ldcg(reinterpret_cast<const float4*>(
                              slotbase + rn * 256 + sb * 32 + sq * 4));
                }
            }
            __syncthreads();
            gemm_chunk(whp, hrow, r, a01, a23);
        }

        // -------- gates / state --------
        float z0, z1, z2, z3;
        asm("mov.b64 {%0, %1}, %2;" : "=f"(z0), "=f"(z1) : "l"(a01));
        asm("mov.b64 {%0, %1}, %2;" : "=f"(z2), "=f"(z3) : "l"(a23));
        float ig = sig_f(z0);
        float fg = sig_f(z1);
        float gg = tanh_f(z2);
        float og = sig_f(z3);
        c = fmaf(fg, c, ig * gg);
        float hn = og * tanh_f(c);

        // -------- epilogue: own slice local + publish to L2 --------
        {
            // local: duplicated pair straight into hd (next step's own chunk)
            *reinterpret_cast<float2*>(hd + b_l * HSTRIDE + 2 * gcol) = make_float2(hn, hn);
            if (s + 1 < TT) {
                __stcg(&g_hx[pn][RB][CB][b_l * 32 + u_l], hn);
            }
            out[(size_t)(gb + b_l) * (TT * UU) + (size_t)s * UU + gcol] = hn;
            if (s == TT - 1 && write_hc) {
                out[(size_t)BB * TT * UU + (size_t)(gb + b_l) * UU + gcol] = hn;
                out[(size_t)BB * TT * UU + (size_t)BB * UU + (size_t)(gb + b_l) * UU + gcol] = c;
            }
        }
        __syncthreads();   // own-slice STS + STGs ordered before next step's flag/compute
    }
}

extern "C" void kernel_launch(void* const* d_in, const int* in_sizes, int n_in,
                              void* d_out, int out_size) {
    const float* x    = (const float*)d_in[0];
    const float* Wx   = (const float*)d_in[1];
    const float* Wh   = (const float*)d_in[2];
    const float* bias = (const float*)d_in[3];
    float* out = (float*)d_out;

    long long need = (long long)BB * TT * UU + 2LL * BB * UU;
    int write_hc = ((long long)out_size >= need) ? 1 : 0;

    cudaFuncSetAttribute(lstm_persistent_kernel,
                         cudaFuncAttributeMaxDynamicSharedMemorySize, SMEM_BYTES);

    lstm_init_kernel<<<256, 256>>>();
    lstm_persistent_kernel<<<NCTA, NTHR, SMEM_BYTES>>>(x, Wx, Wh, bias, out, write_hc);
}

// round 17
// speedup vs baseline: 1.5313x; 1.5313x over previous
#include <cuda_runtime.h>
#include <cstdint>

// LSTM B=128, T=2048, F=3, U=256. 128 CTAs = 16 groups x 8 ranks, 512 threads each.
// R8 = R7 with the alignment fix: HSTRIDE 258 -> 260 floats (1040B, 16B-aligned) so comm
//     warps' float4 staging stores are legal. Warp specialization: warps 0-7 compute
//     (k-pair FFMA2 GEMM from SMEM, activations), warps 8-15 comm (publish own h slice,
//     per-rank release flags, per-rank poll + fetch + stage, ys stores). Named HW barriers.

#define BB 128
#define TT 2048
#define FF 3
#define UU 256
#define G4 1024
#define NCTA 128
#define NTHR 512
#define NCOMP 256

#define BAR_STG  2   // comm arrive, compute sync : remote h staged
#define BAR_HN   3   // compute arrive, comm sync : hn ready
#define BAR_COMM 4   // comm-internal (publish drain)
#define BAR_COMP 5   // compute-internal (own-stage visibility)

__device__ __align__(16) float    g_hx[2][16][8][256];  // [slot][group][rank][b*32+u]
__device__ unsigned g_flag[16][8][32];                  // 128B-spaced per-rank flags

// SMEM layout (float offsets)
#define OFF_WH2  0        // 128 kp * 128 cols * 2 = 32768 : {w_2kp,c , w_2kp+1,c}
#define HSTRIDE  260      // 1040 bytes: 16B-aligned rows (256 data + 4 pad)
#define HD_P     (8 * HSTRIDE)          // 2080
#define OFF_HD   32768    // 2 * HD_P = 4160 : h natural [p][b][k]
#define OFF_HN   36928    // 2 * 256 : hn staging [p][b*32+u]
#define OFF_BIAS 37440    // 128 (permuted c = u*4+g)
#define OFF_WX   37568    // 3*128 (permuted)
#define SMEM_FLOATS 37952
#define SMEM_BYTES (SMEM_FLOATS * 4)

__device__ __forceinline__ float sig_f(float x) {
    x = fminf(fmaxf(x, -30.f), 30.f);
    float e = __expf(-x);
    return __fdividef(1.f, 1.f + e);
}
__device__ __forceinline__ float tanh_f(float x) {
    float ax = fminf(fabsf(x), 15.f);
    float e = __expf(-2.f * ax);
    float r = __fdividef(1.f - e, 1.f + e);
    return copysignf(r, x);
}
__device__ __forceinline__ void ffma2(unsigned long long& acc,
                                      unsigned long long a,
                                      unsigned long long b) {
    asm("fma.rn.f32x2 %0, %1, %2, %0;" : "+l"(acc) : "l"(a), "l"(b));
}
__device__ __forceinline__ unsigned ld_acq(const unsigned* p) {
    unsigned v;
    asm volatile("ld.global.acquire.gpu.u32 %0, [%1];" : "=r"(v) : "l"(p));
    return v;
}
__device__ __forceinline__ void st_rel(unsigned* p, unsigned v) {
    asm volatile("st.global.release.gpu.u32 [%0], %1;" :: "l"(p), "r"(v) : "memory");
}
#define BAR_ARRIVE(id, cnt) asm volatile("bar.arrive %0, %1;" :: "r"(id), "r"(cnt) : "memory")
#define BAR_SYNCN(id, cnt)  asm volatile("bar.sync %0, %1;"   :: "r"(id), "r"(cnt) : "memory")

// 16 k-pairs (32 k) of the GEMM for chunk ch: 3 LDS + 4 FFMA2 per kp.
__device__ __forceinline__ void gemm16(const float* __restrict__ wbase,
                                       const float* __restrict__ hrow, int ch,
                                       unsigned long long& a0, unsigned long long& a1,
                                       unsigned long long& a2, unsigned long long& a3) {
    const float* wk = wbase + ch * (16 * 256);
    const unsigned long long* hp =
        reinterpret_cast<const unsigned long long*>(hrow) + ch * 16;
    #pragma unroll
    for (int q = 0; q < 16; q++) {
        unsigned long long hv = hp[q];                         // {h_2k, h_2k+1}
        ulonglong2 w01 = *reinterpret_cast<const ulonglong2*>(wk + q * 256);
        ulonglong2 w23 = *reinterpret_cast<const ulonglong2*>(wk + q * 256 + 4);
        ffma2(a0, hv, w01.x);
        ffma2(a1, hv, w01.y);
        ffma2(a2, hv, w23.x);
        ffma2(a3, hv, w23.y);
    }
}

__global__ void lstm_init_kernel() {
    int i = blockIdx.x * blockDim.x + threadIdx.x;
    if (i < 2 * 16 * 8 * 256) ((float*)g_hx)[i] = 0.f;
    if (i < 16 * 8 * 32) ((unsigned*)g_flag)[i] = 0u;
}

__global__ void __launch_bounds__(NTHR, 1) lstm_persistent_kernel(
    const float* __restrict__ x,     // [B, T, F]
    const float* __restrict__ Wx,    // [F, 4U]
    const float* __restrict__ Wh,    // [U, 4U]
    const float* __restrict__ bias,  // [4U]
    float* __restrict__ out,         // ys [B,T,U] (+ h_T, c_T if write_hc)
    int write_hc)
{
    extern __shared__ float sm[];
    const int tid = threadIdx.x;
    const int RB  = blockIdx.x >> 3;   // group 0..15
    const int CB  = blockIdx.x & 7;    // rank 0..7
    const int gb  = RB * 8;

    // ---------------- setup (all 512 threads) ----------------
    for (int i = tid; i < 128 * 128; i += NTHR) {
        int kp = i >> 7, c = i & 127;
        int u = c >> 2, g = c & 3;
        int gc = g * UU + CB * 32 + u;
        sm[OFF_WH2 + kp * 256 + c * 2 + 0] = Wh[(2 * kp)     * G4 + gc];
        sm[OFF_WH2 + kp * 256 + c * 2 + 1] = Wh[(2 * kp + 1) * G4 + gc];
    }
    for (int i = tid; i < 3 * 128; i += NTHR) {
        int f = i >> 7, c = i & 127;
        int u = c >> 2, g = c & 3;
        sm[OFF_WX + i] = Wx[f * G4 + g * UU + CB * 32 + u];
    }
    if (tid < 128) {
        int u = tid >> 2, g = tid & 3;
        sm[OFF_BIAS + tid] = bias[g * UU + CB * 32 + u];
    }
    for (int i = tid; i < 2 * HD_P; i += NTHR) sm[OFF_HD + i] = 0.f;  // h(-1) = 0
    __syncthreads();

    if (tid < NCOMP) {
        // ======================= COMPUTE WARPS =======================
        const int u_l = tid >> 3;          // 0..31
        const int b_l = tid & 7;           // 0..7
        const int gcol = CB * 32 + u_l;
        const float* wbase = sm + OFF_WH2 + u_l * 8;
        const float* bsr   = sm + OFF_BIAS + u_l * 4;
        const float* wxr   = sm + OFF_WX + u_l * 4;
        const float* xr0   = x + (size_t)(gb + b_l) * (TT * FF);

        float c = 0.f, hn = 0.f;

        for (int s = 0; s < TT; s++) {
            const int p = s & 1, pn = p ^ 1;
            const float* hrow = sm + OFF_HD + p * HD_P + b_l * HSTRIDE;

            unsigned long long a0, a1, a2, a3;
            {
                float z = 0.f;
                asm("mov.b64 %0, {%1, %1};" : "=l"(a0) : "f"(z));
                a1 = a0; a2 = a0; a3 = a0;
            }

            // x loads (consumed ~3000 cyc later)
            float xp0 = __ldg(xr0 + (size_t)s * FF + 0);
            float xp1 = __ldg(xr0 + (size_t)s * FF + 1);
            float xp2 = __ldg(xr0 + (size_t)s * FF + 2);

            // own chunk: local h, no dependence on comm
            gemm16(wbase, hrow, CB, a0, a1, a2, a3);

            BAR_SYNCN(BAR_STG, NTHR);      // remote h(s-1) staged by comm

            #pragma unroll 1
            for (int ch = 0; ch < 8; ch++) {
                if (ch == CB) continue;
                gemm16(wbase, hrow, ch, a0, a1, a2, a3);
            }

            // fold even/odd partial sums, add bias + x@Wx
            float z0, z1, z2, z3;
            {
                float lo, hi;
                asm("mov.b64 {%0, %1}, %2;" : "=f"(lo), "=f"(hi) : "l"(a0)); z0 = lo + hi;
                asm("mov.b64 {%0, %1}, %2;" : "=f"(lo), "=f"(hi) : "l"(a1)); z1 = lo + hi;
                asm("mov.b64 {%0, %1}, %2;" : "=f"(lo), "=f"(hi) : "l"(a2)); z2 = lo + hi;
                asm("mov.b64 {%0, %1}, %2;" : "=f"(lo), "=f"(hi) : "l"(a3)); z3 = lo + hi;
            }
            {
                float4 bb = *reinterpret_cast<const float4*>(bsr);
                z0 += bb.x; z1 += bb.y; z2 += bb.z; z3 += bb.w;
                float4 w;
                w = *reinterpret_cast<const float4*>(wxr + 0 * 128);
                z0 = fmaf(xp0, w.x, z0); z1 = fmaf(xp0, w.y, z1);
                z2 = fmaf(xp0, w.z, z2); z3 = fmaf(xp0, w.w, z3);
                w = *reinterpret_cast<const float4*>(wxr + 1 * 128);
                z0 = fmaf(xp1, w.x, z0); z1 = fmaf(xp1, w.y, z1);
                z2 = fmaf(xp1, w.z, z2); z3 = fmaf(xp1, w.w, z3);
                w = *reinterpret_cast<const float4*>(wxr + 2 * 128);
                z0 = fmaf(xp2, w.x, z0); z1 = fmaf(xp2, w.y, z1);
                z2 = fmaf(xp2, w.z, z2); z3 = fmaf(xp2, w.w, z3);
            }

            float ig = sig_f(z0);
            float fg = sig_f(z1);
            float gg = tanh_f(z2);
            float og = sig_f(z3);
            c = fmaf(fg, c, ig * gg);
            hn = og * tanh_f(c);

            // stage hn for comm + own slice into next-parity h tile
            sm[OFF_HN + p * 256 + b_l * 32 + u_l] = hn;
            sm[OFF_HD + pn * HD_P + b_l * HSTRIDE + gcol] = hn;

            BAR_ARRIVE(BAR_HN, NTHR);      // release comm
            BAR_SYNCN(BAR_COMP, NCOMP);    // own-stage visible to all compute warps
        }

        if (write_hc) {
            out[(size_t)BB * TT * UU + (size_t)(gb + b_l) * UU + gcol] = hn;
            out[(size_t)BB * TT * UU + (size_t)BB * UU + (size_t)(gb + b_l) * UU + gcol] = c;
        }
    } else {
        // ======================= COMM WARPS =======================
        const int kt   = tid - NCOMP;      // 0..255
        const int j    = kt >> 5;          // handled rank
        const int lane = kt & 31;
        unsigned* jflag  = &g_flag[RB][j][0];
        unsigned* myflag = &g_flag[RB][CB][0];

        for (int s = 0; s < TT; s++) {
            if (s > 0) {
                const int hnp  = (s - 1) & 1;
                const int slot = s & 1;

                // publish h(s-1): coalesced stcg + drain + release flag
                float v = sm[OFF_HN + hnp * 256 + kt];
                __stcg(&g_hx[slot][RB][CB][kt], v);
                BAR_SYNCN(BAR_COMM, NCOMP);
                if (kt == 0) {
                    __threadfence();
                    st_rel(myflag, (unsigned)s);
                }

                if (j == CB) {
                    // own rank's slice is staged by compute; this warp writes ys(s-1)
                    #pragma unroll
                    for (int it = 0; it < 2; it++) {
                        int idx4 = it * 32 + lane;
                        float4 v4 = *reinterpret_cast<const float4*>(
                            sm + OFF_HN + hnp * 256 + idx4 * 4);
                        int b = idx4 >> 3, u = (idx4 & 7) * 4;
                        *reinterpret_cast<float4*>(
                            out + (size_t)(gb + b) * (TT * UU)
                                + (size_t)(s - 1) * UU + CB * 32 + u) = v4;
                    }
                } else {
                    // per-rank poll + fetch + stage (16B-aligned: HSTRIDE=260)
                    unsigned vv;
                    do { vv = ld_acq(jflag); } while (vv < (unsigned)s);
                    const float* src = &g_hx[slot][RB][j][0];
                    #pragma unroll
                    for (int it = 0; it < 2; it++) {
                        int idx4 = it * 32 + lane;
                        float4 v4 = __ldcg(reinterpret_cast<const float4*>(src + idx4 * 4));
                        int b = idx4 >> 3, u = (idx4 & 7) * 4;
                        *reinterpret_cast<float4*>(
                            sm + OFF_HD + slot * HD_P + b * HSTRIDE + j * 32 + u) = v4;
                    }
                }
            }
            BAR_ARRIVE(BAR_STG, NTHR);     // staged (or trivially at s=0)
            BAR_SYNCN(BAR_HN, NTHR);       // wait for hn(s)
        }

        // final ys(TT-1)
        if (j == CB) {
            const int hnp = (TT - 1) & 1;
            #pragma unroll
            for (int it = 0; it < 2; it++) {
                int idx4 = it * 32 + lane;
                float4 v4 = *reinterpret_cast<const float4*>(
                    sm + OFF_HN + hnp * 256 + idx4 * 4);
                int b = idx4 >> 3, u = (idx4 & 7) * 4;
                *reinterpret_cast<float4*>(
                    out + (size_t)(gb + b) * (TT * UU)
                        + (size_t)(TT - 1) * UU + CB * 32 + u) = v4;
            }
        }
    }
}

extern "C" void kernel_launch(void* const* d_in, const int* in_sizes, int n_in,
                              void* d_out, int out_size) {
    const float* x    = (const float*)d_in[0];
    const float* Wx   = (const float*)d_in[1];
    const float* Wh   = (const float*)d_in[2];
    const float* bias = (const float*)d_in[3];
    float* out = (float*)d_out;

    long long need = (long long)BB * TT * UU + 2LL * BB * UU;
    int write_hc = ((long long)out_size >= need) ? 1 : 0;

    cudaFuncSetAttribute(lstm_persistent_kernel,
                         cudaFuncAttributeMaxDynamicSharedMemorySize, SMEM_BYTES);

    lstm_init_kernel<<<256, 256>>>();
    lstm_persistent_kernel<<<NCTA, NTHR, SMEM_BYTES>>>(x, Wx, Wh, bias, out, write_hc);
}